// round 7
// baseline (speedup 1.0000x reference)
#include <cuda_runtime.h>
#include <cuda_bf16.h>
#include <cstdint>

#define N      4096
#define D      64
#define NB     128      // persistent blocks; 1/SM, all co-resident
#define NTHR   256
#define ITERS  100
#define NT     32       // 32x32 grid of 128x128 tiles
#define SA     36       // A smem row stride (uint32): bank = (4r+c)%32, conflict-free
#define SB     20       // B half-tile row stride (uint32): bank = (20r+c)%32, conflict-free

// ---------------- device globals (no allocation allowed) --------------------------
__device__ float         g_K[(size_t)N * N];   // written only for nonzero tiles
__device__ float         g_M[(size_t)N * N];
__device__ __nv_bfloat16 g_x0h[N * D];
__device__ __nv_bfloat16 g_x1h[N * D];
__device__ float         g_sq0_32[N], g_sq0_64[N];
__device__ float         g_sq1_32[N], g_sq1_64[N];
__device__ float         g_u[N], g_v[N];
__device__ unsigned      g_bar_count;          // self-resets to 0 at every barrier
__device__ unsigned      g_bar_phase;          // monotone; compared relatively
__device__ int           g_changed[ITERS];
__device__ float         g_cost;
__device__ int           g_tilemap[NT * NT];

// ---------------- cp.async helpers -------------------------------------------------
__device__ __forceinline__ void cpa16(uint32_t dst, const void* src) {
    asm volatile("cp.async.cg.shared.global [%0], [%1], 16;" :: "r"(dst), "l"(src));
}
#define CP_COMMIT() asm volatile("cp.async.commit_group;")
#define CP_WAIT0()  asm volatile("cp.async.wait_group 0;")

// ---------------- self-resetting grid barrier (all NB blocks co-resident) ---------
__device__ __forceinline__ void gsync() {
    __syncthreads();
    if (threadIdx.x == 0) {
        __threadfence();                               // release
        unsigned ph = atomicAdd(&g_bar_phase, 0u);     // read phase BEFORE arriving
        if (atomicAdd(&g_bar_count, 1u) == (unsigned)NB - 1u) {
            atomicExch(&g_bar_count, 0u);              // reset for next barrier
            atomicAdd(&g_bar_phase, 1u);               // release all spinners
        } else {
            while (atomicAdd(&g_bar_phase, 0u) == ph) __nanosleep(32);
        }
        __threadfence();                               // acquire (L1 invalidate)
    }
    __syncthreads();
}

// ---------------- mma over 2 k-steps (32 dims) from smem ---------------------------
__device__ __forceinline__ void mma2(float (&acc)[4][4][4],
                                     const uint32_t* Ah, const uint32_t* Bh,
                                     int ks0, int AR, int BR, int gid, int pid) {
#pragma unroll
    for (int kk = 0; kk < 2; kk++) {
        const int ks = ks0 + kk;
        const int ac = ks * 8 + pid;      // A col in full 64-dim layout
        const int bc = kk * 8 + pid;      // B col within the 32-dim half buffer
        uint32_t a[4][4], b[4][2];
#pragma unroll
        for (int mi = 0; mi < 4; mi++) {
            int r = AR + mi * 16 + gid;
            a[mi][0] = Ah[r * SA + ac];
            a[mi][1] = Ah[(r + 8) * SA + ac];
            a[mi][2] = Ah[r * SA + ac + 4];
            a[mi][3] = Ah[(r + 8) * SA + ac + 4];
        }
#pragma unroll
        for (int ni = 0; ni < 4; ni++) {
            int c = BR + ni * 8 + gid;
            b[ni][0] = Bh[c * SB + bc];
            b[ni][1] = Bh[c * SB + bc + 4];
        }
#pragma unroll
        for (int mi = 0; mi < 4; mi++)
#pragma unroll
            for (int ni = 0; ni < 4; ni++)
                asm volatile(
                    "mma.sync.aligned.m16n8k16.row.col.f32.bf16.bf16.f32 "
                    "{%0,%1,%2,%3}, {%4,%5,%6,%7}, {%8,%9}, {%0,%1,%2,%3};"
                    : "+f"(acc[mi][ni][0]), "+f"(acc[mi][ni][1]),
                      "+f"(acc[mi][ni][2]), "+f"(acc[mi][ni][3])
                    : "r"(a[mi][0]), "r"(a[mi][1]), "r"(a[mi][2]), "r"(a[mi][3]),
                      "r"(b[ni][0]), "r"(b[ni][1]));
    }
}

// =============== the whole pipeline in ONE persistent kernel =======================
__global__ void __launch_bounds__(NTHR, 1) kern_all(const float* __restrict__ x0,
                                                    const float* __restrict__ x1,
                                                    float* __restrict__ out) {
    // smem pool: Ah[128*36] | B0a[128*20] | B0b[128*20] | B1[128*20]  = 49152 B
    __shared__ uint32_t s_pool[12288];
    uint32_t* const Ah = s_pool;
    uint32_t* const B0[2] = { s_pool + 4608, s_pool + 7168 };
    uint32_t* const B1 = s_pool + 9728;
    float* const sred = (float*)s_pool;       // phase-2 overlay

    const int tid  = threadIdx.x;
    const int bid  = blockIdx.x;
    const int lane = tid & 31;
    const int w    = tid >> 5;
    const int gid  = lane >> 2;
    const int pid  = lane & 3;
    const int wm   = w >> 2;                  // 0..1
    const int wn   = w & 3;                   // 0..3

    // =========== phase 0: convert fp32 -> bf16, partial + full row norms ==========
    if (bid == 0) {
        if (tid == 0) g_cost = 0.0f;
        if (tid < ITERS) g_changed[tid] = 0;
    }
    {
        int g   = bid * NTHR + tid;           // 0..32767 = 8192 rows x 4 quarters
        int row = g >> 2;
        int q   = g & 3;                      // 16 dims per quarter
        const float* src = (row < N) ? x0 + (size_t)row * D
                                     : x1 + (size_t)(row - N) * D;
        uint32_t* dsth = (row < N) ? (uint32_t*)g_x0h + (size_t)row * 32
                                   : (uint32_t*)g_x1h + (size_t)(row - N) * 32;
        float s = 0.0f;
#pragma unroll
        for (int i = 0; i < 4; i++) {
            float4 v4 = *(const float4*)(src + q * 16 + i * 4);
            s += v4.x * v4.x + v4.y * v4.y + v4.z * v4.z + v4.w * v4.w;
            __nv_bfloat162 p0 = __floats2bfloat162_rn(v4.x, v4.y);
            __nv_bfloat162 p1 = __floats2bfloat162_rn(v4.z, v4.w);
            dsth[q * 8 + i * 2]     = *(uint32_t*)&p0;
            dsth[q * 8 + i * 2 + 1] = *(uint32_t*)&p1;
        }
        float s1 = s  + __shfl_xor_sync(0xffffffffu, s,  1);   // q01 / q23 pairs
        float s2 = s1 + __shfl_xor_sync(0xffffffffu, s1, 2);   // full row
        if (q == 0) {
            if (row < N) { g_sq0_32[row] = s1; g_sq0_64[row] = s2; }
            else         { g_sq1_32[row - N] = s1; g_sq1_64[row - N] = s2; }
        }
    }
    gsync();

    // =========== phase 1: screened GEMM, 8 tiles per block ========================
    {
        const int rs = bid >> 2;              // row slab 0..31 (A reused 8x)
        const int cg = bid & 3;               // col group: tiles cg*8 .. cg*8+7
        const uint32_t sb = (uint32_t)__cvta_generic_to_shared(s_pool);
        const uint32_t offB0[2] = { 4608u * 4u, 7168u * 4u };
        const uint32_t offB1 = 9728u * 4u;

        // A slab (full 64 dims): 1024 uint4, 4/thread
        {
            const uint4* GA = (const uint4*)(g_x0h + (size_t)rs * 128 * D);
#pragma unroll
            for (int i = 0; i < 4; i++) {
                int f = tid + i * NTHR; int r = f >> 3; int c4 = f & 7;
                cpa16(sb + (uint32_t)(r * SA + c4 * 4) * 4u, GA + r * 8 + c4);
            }
        }
        // B half-tile loader: 512 uint4, 2/thread
        auto loadBhalf = [&](uint32_t off, int ct, int half) {
            const uint4* GB = (const uint4*)(g_x1h + (size_t)ct * 128 * D);
#pragma unroll
            for (int i = 0; i < 2; i++) {
                int f = tid + i * NTHR; int r = f >> 2; int c4 = f & 3;
                cpa16(sb + off + (uint32_t)(r * SB + c4 * 4) * 4u,
                      GB + r * 8 + c4 + half * 4);
            }
        };
        loadBhalf(offB0[0], cg * 8, 0);
        CP_COMMIT();

        // hoist sq0 for this slab into registers (fixed across the 8 tiles)
        const int gr = rs * 128 + wm * 64;
        float r032[4][2], r064[4][2];
#pragma unroll
        for (int mi = 0; mi < 4; mi++) {
            r032[mi][0] = g_sq0_32[gr + mi * 16 + gid];
            r032[mi][1] = g_sq0_32[gr + mi * 16 + gid + 8];
            r064[mi][0] = g_sq0_64[gr + mi * 16 + gid];
            r064[mi][1] = g_sq0_64[gr + mi * 16 + gid + 8];
        }

        const int AR = wm * 64, BR = wn * 32;
        int cur = 0;
        for (int k = 0; k < 8; k++) {
            const int ct = cg * 8 + k;
            CP_WAIT0(); __syncthreads();

            float acc[4][4][4];
#pragma unroll
            for (int mi = 0; mi < 4; mi++)
#pragma unroll
                for (int ni = 0; ni < 4; ni++)
#pragma unroll
                    for (int f = 0; f < 4; f++) acc[mi][ni][f] = 0.0f;

            mma2(acc, Ah, B0[cur], 0, AR, BR, gid, pid);       // dims 0..31

            if (k < 7) { loadBhalf(offB0[cur ^ 1], ct + 1, 0); CP_COMMIT(); }

            // ---- exact screen: partial M (dims 0..31) is a lower bound on M ----
            const int gc = ct * 128 + wn * 32;
            int need = 0;
#pragma unroll
            for (int mi = 0; mi < 4; mi++)
#pragma unroll
                for (int ni = 0; ni < 4; ni++) {
                    int c = gc + ni * 8 + 2 * pid;
                    float s1a = g_sq1_32[c], s1b = g_sq1_32[c + 1];
                    float m0 = fmaf(-2.0f, acc[mi][ni][0], r032[mi][0] + s1a);
                    float m1 = fmaf(-2.0f, acc[mi][ni][1], r032[mi][0] + s1b);
                    float m2 = fmaf(-2.0f, acc[mi][ni][2], r032[mi][1] + s1a);
                    float m3 = fmaf(-2.0f, acc[mi][ni][3], r032[mi][1] + s1b);
                    need |= (fminf(fminf(m0, m1), fminf(m2, m3)) < 11.0f) ? 1 : 0;
                }
            int mapv = 0;
            if (__syncthreads_or(need)) {
                // rare: finish dims 32..63 exactly
                loadBhalf(offB1, ct, 1); CP_COMMIT();
                CP_WAIT0(); __syncthreads();
                mma2(acc, Ah, B1, 2, AR, BR, gid, pid);

                int need2 = 0;
                float mv[4][4][4];
#pragma unroll
                for (int mi = 0; mi < 4; mi++)
#pragma unroll
                    for (int ni = 0; ni < 4; ni++) {
                        int c = gc + ni * 8 + 2 * pid;
                        float s1a = g_sq1_64[c], s1b = g_sq1_64[c + 1];
                        float m0 = fmaxf(fmaf(-2.0f, acc[mi][ni][0], r064[mi][0] + s1a), 0.0f);
                        float m1 = fmaxf(fmaf(-2.0f, acc[mi][ni][1], r064[mi][0] + s1b), 0.0f);
                        float m2 = fmaxf(fmaf(-2.0f, acc[mi][ni][2], r064[mi][1] + s1a), 0.0f);
                        float m3 = fmaxf(fmaf(-2.0f, acc[mi][ni][3], r064[mi][1] + s1b), 0.0f);
                        mv[mi][ni][0] = m0; mv[mi][ni][1] = m1;
                        mv[mi][ni][2] = m2; mv[mi][ni][3] = m3;
                        need2 |= (fminf(fminf(m0, m1), fminf(m2, m3)) < 11.0f) ? 1 : 0;
                    }
                mapv = __syncthreads_or(need2);
                if (mapv) {
#pragma unroll
                    for (int mi = 0; mi < 4; mi++)
#pragma unroll
                        for (int ni = 0; ni < 4; ni++) {
                            int r0 = gr + mi * 16 + gid;
                            int c  = gc + ni * 8 + 2 * pid;
                            float m0 = mv[mi][ni][0], m1 = mv[mi][ni][1];
                            float m2 = mv[mi][ni][2], m3 = mv[mi][ni][3];
                            *(float2*)(g_M + (size_t)r0 * N + c)       = make_float2(m0, m1);
                            *(float2*)(g_M + (size_t)(r0 + 8) * N + c) = make_float2(m2, m3);
                            *(float2*)(g_K + (size_t)r0 * N + c)       =
                                make_float2(expf(-10.0f * m0), expf(-10.0f * m1));
                            *(float2*)(g_K + (size_t)(r0 + 8) * N + c) =
                                make_float2(expf(-10.0f * m2), expf(-10.0f * m3));
                        }
                }
            }
            if (tid == 0) g_tilemap[rs * NT + ct] = mapv;
            cur ^= 1;
        }
    }
    gsync();

    // =========== phase 2: Sinkhorn (or exact zero fast path) ======================
    {
        int loc = 0;
        for (int t = tid; t < NT * NT; t += NTHR) loc |= g_tilemap[t];
        if (!__syncthreads_or(loc)) {
            if (bid == 0 && tid == 0) out[0] = 0.0f;   // P == 0 exactly -> cost == 0
            return;                                     // uniform across all blocks
        }
    }

    const float AB    = 1.0f / (float)N;
    const float DELTA = 1e-8f;
    {
        int gi = bid * NTHR + tid;
        if (gi < N) { g_u[gi] = 1.0f; g_v[gi] = 1.0f; }
    }
    gsync();

    for (int it = 0; it < ITERS; it++) {
        // u-pass: warp-per-row, skip all-zero tiles
#pragma unroll
        for (int rr = 0; rr < 4; rr++) {
            int r  = bid * 32 + w * 4 + rr;
            int rt = r >> 7;
            const int* map = g_tilemap + rt * NT;
            const float4* kr = (const float4*)(g_K + (size_t)r * N);
            const float4* vv = (const float4*)g_v;
            float s = 0.0f;
            for (int ct = 0; ct < NT; ct++) {
                if (!map[ct]) continue;
                int j = ct * 32 + lane;
                float4 kq = kr[j];
                float4 vq = vv[j];
                s += kq.x * vq.x + kq.y * vq.y + kq.z * vq.z + kq.w * vq.w;
            }
#pragma unroll
            for (int o = 16; o; o >>= 1) s += __shfl_xor_sync(0xffffffffu, s, o);
            if (lane == 0) {
                float un = AB / (s + DELTA);
                if (un != g_u[r]) g_changed[it] = 1;
                g_u[r] = un;
            }
        }
        gsync();

        // v-pass: 32-col stripe per block, skip all-zero tiles
        {
            int c  = bid * 32 + lane;
            int ct = bid >> 2;
            float s = 0.0f;
            for (int rt = 0; rt < NT; rt++) {
                if (!g_tilemap[rt * NT + ct]) continue;
                int rbase = rt * 128;
#pragma unroll 4
                for (int r = rbase + w; r < rbase + 128; r += 8)
                    s += g_K[(size_t)r * N + c] * g_u[r];
            }
            sred[tid] = s;
            __syncthreads();
            if (tid < 32) {
                float t = sred[tid];
#pragma unroll
                for (int g = 1; g < 8; g++) t += sred[tid + g * 32];
                float vn = AB / (t + DELTA);
                if (vn != g_v[c]) g_changed[it] = 1;
                g_v[c] = vn;
            }
        }
        gsync();

        if (g_changed[it] == 0) break;    // exact bitwise fixed point (uniform)
    }

    // cost = sum_ij u_i * K_ij * v_j * M_ij (zero tiles contribute exactly 0)
    {
        float wsum = 0.0f;
#pragma unroll
        for (int rr = 0; rr < 4; rr++) {
            int r  = bid * 32 + w * 4 + rr;
            int rt = r >> 7;
            const int* map = g_tilemap + rt * NT;
            const float4* kr = (const float4*)(g_K + (size_t)r * N);
            const float4* mr = (const float4*)(g_M + (size_t)r * N);
            const float4* vv = (const float4*)g_v;
            float s = 0.0f;
            for (int ct = 0; ct < NT; ct++) {
                if (!map[ct]) continue;
                int j = ct * 32 + lane;
                float4 kq = kr[j];
                float4 mq = mr[j];
                float4 vq = vv[j];
                s += kq.x * mq.x * vq.x + kq.y * mq.y * vq.y
                   + kq.z * mq.z * vq.z + kq.w * mq.w * vq.w;
            }
#pragma unroll
            for (int o = 16; o; o >>= 1) s += __shfl_xor_sync(0xffffffffu, s, o);
            if (lane == 0) wsum += s * g_u[r];
        }
        if (lane == 0) atomicAdd(&g_cost, wsum);
    }
    gsync();
    if (bid == 0 && tid == 0) out[0] = g_cost;
}

// ---------------- launch: ONE kernel ----------------------------------------------
extern "C" void kernel_launch(void* const* d_in, const int* in_sizes, int n_in,
                              void* d_out, int out_size) {
    const float* x0 = (const float*)d_in[0];
    const float* x1 = (const float*)d_in[1];
    float* out = (float*)d_out;
    kern_all<<<NB, NTHR>>>(x0, x1, out);
}

// round 8
// speedup vs baseline: 1.1411x; 1.1411x over previous
#include <cuda_runtime.h>
#include <cuda_bf16.h>
#include <cstdint>

#define N      4096
#define D      64
#define NB     128      // persistent blocks; 1/SM, all co-resident
#define NTHR   256
#define ITERS  100
#define NT     32       // 32x32 grid of 128x128 tiles
#define SA     36       // A smem row stride (uint32): bank=(4r+c)%32, conflict-free
#define SBH    20       // B half-tile row stride (uint32): bank=(20r+c)%32, conflict-free

// ---------------- device globals (no allocation allowed) --------------------------
__device__ float         g_K[(size_t)N * N];   // written only for nonzero tiles
__device__ float         g_M[(size_t)N * N];
__device__ uint32_t      g_x0h[N * 32];        // A bf16, full rows (32 uint32/row)
__device__ uint32_t      g_x1l[N * 16];        // B bf16 dims 0..31  (16 uint32/row)
__device__ uint32_t      g_x1h2[N * 16];       // B bf16 dims 32..63 (16 uint32/row)
__device__ float         g_sq0_32[N], g_sq0_64[N];
__device__ float         g_sq1_32[N], g_sq1_64[N];
__device__ float         g_u[N], g_v[N];
__device__ unsigned      g_bar_count;          // self-resets to 0 at every barrier
__device__ unsigned      g_bar_phase;          // monotone; compared relatively
__device__ int           g_changed[ITERS];
__device__ float         g_cost;
__device__ int           g_tilemap[NT * NT];
__device__ int           g_blockany[NB];       // per-block OR of its tile flags

// ---------------- cp.async helpers -------------------------------------------------
__device__ __forceinline__ void cpa16(uint32_t dst, const void* src) {
    asm volatile("cp.async.cg.shared.global [%0], [%1], 16;" :: "r"(dst), "l"(src));
}
#define CP_COMMIT() asm volatile("cp.async.commit_group;")
#define CP_WAIT0()  asm volatile("cp.async.wait_group 0;")

// ---------------- self-resetting grid barrier --------------------------------------
__device__ __forceinline__ void gsync() {
    __syncthreads();
    if (threadIdx.x == 0) {
        __threadfence();
        unsigned ph = atomicAdd(&g_bar_phase, 0u);
        if (atomicAdd(&g_bar_count, 1u) == (unsigned)NB - 1u) {
            atomicExch(&g_bar_count, 0u);
            atomicAdd(&g_bar_phase, 1u);
        } else {
            while (atomicAdd(&g_bar_phase, 0u) == ph) __nanosleep(32);
        }
        __threadfence();
    }
    __syncthreads();
}

// ---------------- mma over 2 k-steps (dims lo) from smem ---------------------------
__device__ __forceinline__ void mma2(float (&acc)[4][4][4],
                                     const uint32_t* Ah, const uint32_t* Bh,
                                     int AR, int BR, int gid, int pid) {
#pragma unroll
    for (int kk = 0; kk < 2; kk++) {
        const int ac = kk * 8 + pid;
        const int bc = kk * 8 + pid;
        uint32_t a[4][4], b[4][2];
#pragma unroll
        for (int mi = 0; mi < 4; mi++) {
            int r = AR + mi * 16 + gid;
            a[mi][0] = Ah[r * SA + ac];
            a[mi][1] = Ah[(r + 8) * SA + ac];
            a[mi][2] = Ah[r * SA + ac + 4];
            a[mi][3] = Ah[(r + 8) * SA + ac + 4];
        }
#pragma unroll
        for (int ni = 0; ni < 4; ni++) {
            int c = BR + ni * 8 + gid;
            b[ni][0] = Bh[c * SBH + bc];
            b[ni][1] = Bh[c * SBH + bc + 4];
        }
#pragma unroll
        for (int mi = 0; mi < 4; mi++)
#pragma unroll
            for (int ni = 0; ni < 4; ni++)
                asm volatile(
                    "mma.sync.aligned.m16n8k16.row.col.f32.bf16.bf16.f32 "
                    "{%0,%1,%2,%3}, {%4,%5,%6,%7}, {%8,%9}, {%0,%1,%2,%3};"
                    : "+f"(acc[mi][ni][0]), "+f"(acc[mi][ni][1]),
                      "+f"(acc[mi][ni][2]), "+f"(acc[mi][ni][3])
                    : "r"(a[mi][0]), "r"(a[mi][1]), "r"(a[mi][2]), "r"(a[mi][3]),
                      "r"(b[ni][0]), "r"(b[ni][1]));
    }
}

// ---------------- rare path: hi dims, B fragments straight from global --------------
__device__ __forceinline__ void mma2g_hi(float (&acc)[4][4][4],
                                         const uint32_t* Ah, int ct,
                                         int AR, int BR, int gid, int pid) {
#pragma unroll
    for (int kk = 0; kk < 2; kk++) {
        const int ac = (2 + kk) * 8 + pid;
        const int bc = kk * 8 + pid;
        uint32_t a[4][4], b[4][2];
#pragma unroll
        for (int mi = 0; mi < 4; mi++) {
            int r = AR + mi * 16 + gid;
            a[mi][0] = Ah[r * SA + ac];
            a[mi][1] = Ah[(r + 8) * SA + ac];
            a[mi][2] = Ah[r * SA + ac + 4];
            a[mi][3] = Ah[(r + 8) * SA + ac + 4];
        }
#pragma unroll
        for (int ni = 0; ni < 4; ni++) {
            int c = ct * 128 + BR + ni * 8 + gid;
            b[ni][0] = g_x1h2[(size_t)c * 16 + bc];
            b[ni][1] = g_x1h2[(size_t)c * 16 + bc + 4];
        }
#pragma unroll
        for (int mi = 0; mi < 4; mi++)
#pragma unroll
            for (int ni = 0; ni < 4; ni++)
                asm volatile(
                    "mma.sync.aligned.m16n8k16.row.col.f32.bf16.bf16.f32 "
                    "{%0,%1,%2,%3}, {%4,%5,%6,%7}, {%8,%9}, {%0,%1,%2,%3};"
                    : "+f"(acc[mi][ni][0]), "+f"(acc[mi][ni][1]),
                      "+f"(acc[mi][ni][2]), "+f"(acc[mi][ni][3])
                    : "r"(a[mi][0]), "r"(a[mi][1]), "r"(a[mi][2]), "r"(a[mi][3]),
                      "r"(b[ni][0]), "r"(b[ni][1]));
    }
}

// =============== the whole pipeline in ONE persistent kernel =======================
__global__ void __launch_bounds__(NTHR, 1) kern_all(const float* __restrict__ x0,
                                                    const float* __restrict__ x1,
                                                    float* __restrict__ out) {
    // smem pool: Ah[4608] | B0a[2560] | B0b[2560] | sq1s[1024]  = 43 KB
    __shared__ uint32_t s_pool[10752];
    uint32_t* const Ah = s_pool;
    uint32_t* const B0[2] = { s_pool + 4608, s_pool + 7168 };
    float* const sq1s = (float*)(s_pool + 9728);   // 1024 staged sq1_32 values
    float* const sred = (float*)s_pool;            // phase-2 overlay

    const int tid  = threadIdx.x;
    const int bid  = blockIdx.x;
    const int lane = tid & 31;
    const int w    = tid >> 5;
    const int gid  = lane >> 2;
    const int pid  = lane & 3;
    const int wm   = w >> 2;                  // 0..1
    const int wn   = w & 3;                   // 0..3

    // =========== phase 0: fp32 -> bf16 (x1 split lo/hi), partial + full norms =====
    if (bid == 0) {
        if (tid == 0) g_cost = 0.0f;
        if (tid < ITERS) g_changed[tid] = 0;
    }
    {
        int g   = bid * NTHR + tid;           // 0..32767 = 8192 rows x 4 quarters
        int row = g >> 2;
        int q   = g & 3;                      // 16 dims per quarter
        const float* src = (row < N) ? x0 + (size_t)row * D
                                     : x1 + (size_t)(row - N) * D;
        uint32_t* dsth;
        int base;
        if (row < N) { dsth = g_x0h + (size_t)row * 32; base = q * 8; }
        else {
            int r1 = row - N;
            if (q < 2) { dsth = g_x1l  + (size_t)r1 * 16; base = q * 8; }
            else       { dsth = g_x1h2 + (size_t)r1 * 16; base = (q - 2) * 8; }
        }
        float s = 0.0f;
#pragma unroll
        for (int i = 0; i < 4; i++) {
            float4 v4 = *(const float4*)(src + q * 16 + i * 4);
            s += v4.x * v4.x + v4.y * v4.y + v4.z * v4.z + v4.w * v4.w;
            __nv_bfloat162 p0 = __floats2bfloat162_rn(v4.x, v4.y);
            __nv_bfloat162 p1 = __floats2bfloat162_rn(v4.z, v4.w);
            dsth[base + i * 2]     = *(uint32_t*)&p0;
            dsth[base + i * 2 + 1] = *(uint32_t*)&p1;
        }
        float s1 = s  + __shfl_xor_sync(0xffffffffu, s,  1);   // 32-dim halves
        float s2 = s1 + __shfl_xor_sync(0xffffffffu, s1, 2);   // full row
        if (q == 0) {
            if (row < N) { g_sq0_32[row] = s1; g_sq0_64[row] = s2; }
            else         { g_sq1_32[row - N] = s1; g_sq1_64[row - N] = s2; }
        }
    }
    gsync();

    // =========== phase 1: screened GEMM, 8 tiles per block ========================
    {
        const int rs = bid >> 2;              // row slab 0..31 (A reused 8x)
        const int cg = bid & 3;               // col group: tiles cg*8 .. cg*8+7
        const uint32_t sb = (uint32_t)__cvta_generic_to_shared(s_pool);
        const uint32_t offB0[2] = { 4608u * 4u, 7168u * 4u };

        // stage sq1_32 for this block's 1024 columns into smem (coalesced)
#pragma unroll
        for (int i = 0; i < 4; i++)
            sq1s[tid + i * NTHR] = g_sq1_32[cg * 1024 + tid + i * NTHR];

        // A slab (full 64 dims): 1024 uint4, 4/thread
        {
            const uint4* GA = (const uint4*)(g_x0h + (size_t)rs * 128 * 32);
#pragma unroll
            for (int i = 0; i < 4; i++) {
                int f = tid + i * NTHR; int r = f >> 3; int c4 = f & 7;
                cpa16(sb + (uint32_t)(r * SA + c4 * 4) * 4u, GA + r * 8 + c4);
            }
        }
        // B half-tile loader: tile is one contiguous 8 KB block of g_x1l
        auto loadBlo = [&](uint32_t off, int ct) {
            const uint4* GB = (const uint4*)g_x1l + (size_t)ct * 512;
#pragma unroll
            for (int i = 0; i < 2; i++) {
                int f = tid + i * NTHR; int r = f >> 2; int c4 = f & 3;
                cpa16(sb + off + (uint32_t)(r * SBH + c4 * 4) * 4u, GB + f);
            }
        };
        loadBlo(offB0[0], cg * 8);
        CP_COMMIT();

        // hoist sq0 for this slab into registers (fixed across the 8 tiles)
        const int gr = rs * 128 + wm * 64;
        float r032[4][2], r064[4][2];
#pragma unroll
        for (int mi = 0; mi < 4; mi++) {
            r032[mi][0] = g_sq0_32[gr + mi * 16 + gid];
            r032[mi][1] = g_sq0_32[gr + mi * 16 + gid + 8];
            r064[mi][0] = g_sq0_64[gr + mi * 16 + gid];
            r064[mi][1] = g_sq0_64[gr + mi * 16 + gid + 8];
        }

        const int AR = wm * 64, BR = wn * 32;
        int blkany = 0;
        int cur = 0;
        for (int k = 0; k < 8; k++) {
            const int ct = cg * 8 + k;
            CP_WAIT0(); __syncthreads();

            // prefetch k+1 FIRST: buffer cur^1 is free, latency hides behind mma
            if (k < 7) { loadBlo(offB0[cur ^ 1], ct + 1); CP_COMMIT(); }

            float acc[4][4][4];
#pragma unroll
            for (int mi = 0; mi < 4; mi++)
#pragma unroll
                for (int ni = 0; ni < 4; ni++)
#pragma unroll
                    for (int f = 0; f < 4; f++) acc[mi][ni][f] = 0.0f;

            mma2(acc, Ah, B0[cur], AR, BR, gid, pid);          // dims 0..31

            // ---- exact screen: partial M (dims 0..31) is a lower bound on M ----
            const int lc0 = k * 128 + wn * 32;                 // col within group
            int need = 0;
#pragma unroll
            for (int mi = 0; mi < 4; mi++)
#pragma unroll
                for (int ni = 0; ni < 4; ni++) {
                    int c = lc0 + ni * 8 + 2 * pid;
                    float s1a = sq1s[c], s1b = sq1s[c + 1];
                    float m0 = fmaf(-2.0f, acc[mi][ni][0], r032[mi][0] + s1a);
                    float m1 = fmaf(-2.0f, acc[mi][ni][1], r032[mi][0] + s1b);
                    float m2 = fmaf(-2.0f, acc[mi][ni][2], r032[mi][1] + s1a);
                    float m3 = fmaf(-2.0f, acc[mi][ni][3], r032[mi][1] + s1b);
                    need |= (fminf(fminf(m0, m1), fminf(m2, m3)) < 11.0f) ? 1 : 0;
                }
            int mapv = 0;
            if (__syncthreads_or(need)) {
                // rare: finish dims 32..63 exactly (B frags direct from global)
                mma2g_hi(acc, Ah, ct, AR, BR, gid, pid);
                const int gc = ct * 128 + wn * 32;
                int need2 = 0;
#pragma unroll
                for (int mi = 0; mi < 4; mi++)
#pragma unroll
                    for (int ni = 0; ni < 4; ni++) {
                        int c = gc + ni * 8 + 2 * pid;
                        float s1a = g_sq1_64[c], s1b = g_sq1_64[c + 1];
                        float m0 = fmaxf(fmaf(-2.0f, acc[mi][ni][0], r064[mi][0] + s1a), 0.0f);
                        float m1 = fmaxf(fmaf(-2.0f, acc[mi][ni][1], r064[mi][0] + s1b), 0.0f);
                        float m2 = fmaxf(fmaf(-2.0f, acc[mi][ni][2], r064[mi][1] + s1a), 0.0f);
                        float m3 = fmaxf(fmaf(-2.0f, acc[mi][ni][3], r064[mi][1] + s1b), 0.0f);
                        need2 |= (fminf(fminf(m0, m1), fminf(m2, m3)) < 11.0f) ? 1 : 0;
                        int r0 = gr + mi * 16 + gid;
                        *(float2*)(g_M + (size_t)r0 * N + c)       = make_float2(m0, m1);
                        *(float2*)(g_M + (size_t)(r0 + 8) * N + c) = make_float2(m2, m3);
                        *(float2*)(g_K + (size_t)r0 * N + c)       =
                            make_float2(expf(-10.0f * m0), expf(-10.0f * m1));
                        *(float2*)(g_K + (size_t)(r0 + 8) * N + c) =
                            make_float2(expf(-10.0f * m2), expf(-10.0f * m3));
                    }
                mapv = __syncthreads_or(need2);
            }
            if (tid == 0) g_tilemap[rs * NT + ct] = mapv;
            blkany |= mapv;
            cur ^= 1;
        }
        if (tid == 0) g_blockany[bid] = blkany;
    }
    gsync();

    // =========== phase 2: Sinkhorn (or exact zero fast path) ======================
    {
        int loc = (tid < NB) ? g_blockany[tid] : 0;
        if (!__syncthreads_or(loc)) {
            if (bid == 0 && tid == 0) out[0] = 0.0f;   // P == 0 exactly -> cost == 0
            return;                                     // uniform across all blocks
        }
    }

    const float AB    = 1.0f / (float)N;
    const float DELTA = 1e-8f;
    {
        int gi = bid * NTHR + tid;
        if (gi < N) { g_u[gi] = 1.0f; g_v[gi] = 1.0f; }
    }
    gsync();

    for (int it = 0; it < ITERS; it++) {
        // u-pass: warp-per-row, skip all-zero tiles
#pragma unroll
        for (int rr = 0; rr < 4; rr++) {
            int r  = bid * 32 + w * 4 + rr;
            int rt = r >> 7;
            const int* map = g_tilemap + rt * NT;
            const float4* kr = (const float4*)(g_K + (size_t)r * N);
            const float4* vv = (const float4*)g_v;
            float s = 0.0f;
            for (int ct = 0; ct < NT; ct++) {
                if (!map[ct]) continue;
                int j = ct * 32 + lane;
                float4 kq = kr[j];
                float4 vq = vv[j];
                s += kq.x * vq.x + kq.y * vq.y + kq.z * vq.z + kq.w * vq.w;
            }
#pragma unroll
            for (int o = 16; o; o >>= 1) s += __shfl_xor_sync(0xffffffffu, s, o);
            if (lane == 0) {
                float un = AB / (s + DELTA);
                if (un != g_u[r]) g_changed[it] = 1;
                g_u[r] = un;
            }
        }
        gsync();

        // v-pass: 32-col stripe per block, skip all-zero tiles
        {
            int c  = bid * 32 + lane;
            int ct = bid >> 2;
            float s = 0.0f;
            for (int rt = 0; rt < NT; rt++) {
                if (!g_tilemap[rt * NT + ct]) continue;
                int rbase = rt * 128;
#pragma unroll 4
                for (int r = rbase + w; r < rbase + 128; r += 8)
                    s += g_K[(size_t)r * N + c] * g_u[r];
            }
            sred[tid] = s;
            __syncthreads();
            if (tid < 32) {
                float t = sred[tid];
#pragma unroll
                for (int g = 1; g < 8; g++) t += sred[tid + g * 32];
                float vn = AB / (t + DELTA);
                if (vn != g_v[c]) g_changed[it] = 1;
                g_v[c] = vn;
            }
        }
        gsync();

        if (g_changed[it] == 0) break;    // exact bitwise fixed point (uniform)
    }

    // cost = sum_ij u_i * K_ij * v_j * M_ij (zero tiles contribute exactly 0)
    {
        float wsum = 0.0f;
#pragma unroll
        for (int rr = 0; rr < 4; rr++) {
            int r  = bid * 32 + w * 4 + rr;
            int rt = r >> 7;
            const int* map = g_tilemap + rt * NT;
            const float4* kr = (const float4*)(g_K + (size_t)r * N);
            const float4* mr = (const float4*)(g_M + (size_t)r * N);
            const float4* vv = (const float4*)g_v;
            float s = 0.0f;
            for (int ct = 0; ct < NT; ct++) {
                if (!map[ct]) continue;
                int j = ct * 32 + lane;
                float4 kq = kr[j];
                float4 mq = mr[j];
                float4 vq = vv[j];
                s += kq.x * mq.x * vq.x + kq.y * mq.y * vq.y
                   + kq.z * mq.z * vq.z + kq.w * mq.w * vq.w;
            }
#pragma unroll
            for (int o = 16; o; o >>= 1) s += __shfl_xor_sync(0xffffffffu, s, o);
            if (lane == 0) wsum += s * g_u[r];
        }
        if (lane == 0) atomicAdd(&g_cost, wsum);
    }
    gsync();
    if (bid == 0 && tid == 0) out[0] = g_cost;
}

// ---------------- launch: ONE kernel ----------------------------------------------
extern "C" void kernel_launch(void* const* d_in, const int* in_sizes, int n_in,
                              void* d_out, int out_size) {
    const float* x0 = (const float*)d_in[0];
    const float* x1 = (const float*)d_in[1];
    float* out = (float*)d_out;
    kern_all<<<NB, NTHR>>>(x0, x1, out);
}